// round 8
// baseline (speedup 1.0000x reference)
#include <cuda_runtime.h>
#include <cstdint>

#define N_NODES 100000
#define D 128
#define N_EDGES 1600000
#define TILE 32
#define NTILES (N_NODES / TILE)                  // 3125 exact
#define NB_SCAN ((N_NODES + 255) / 256)          // 391

__device__ int g_cnt[N_NODES];
__device__ int g_rs[N_NODES + 1];
__device__ int g_esrc[N_EDGES];
__device__ int g_bsum[512];
__device__ int g_is64;

// ---------------- helpers ----------------
__device__ __forceinline__ uint32_t f2tf(float x) {
    uint32_t r;
    asm("cvt.rna.tf32.f32 %0, %1;" : "=r"(r) : "f"(x));
    return r;
}
__device__ __forceinline__ void mma_tf32(float d[4], const uint32_t a[4],
                                         const uint32_t b[2]) {
    asm volatile(
        "mma.sync.aligned.m16n8k8.row.col.f32.tf32.tf32.f32 "
        "{%0,%1,%2,%3}, {%4,%5,%6,%7}, {%8,%9}, {%0,%1,%2,%3};"
        : "+f"(d[0]), "+f"(d[1]), "+f"(d[2]), "+f"(d[3])
        : "r"(a[0]), "r"(a[1]), "r"(a[2]), "r"(a[3]), "r"(b[0]), "r"(b[1]));
}

__device__ __forceinline__ void load_edge(const void* src_raw, const void* dst_raw,
                                          int e, int is64, int& s, int& d) {
    if (is64) {
        s = (int)((const long long*)src_raw)[e];
        d = (int)((const long long*)dst_raw)[e];
    } else {
        s = ((const int*)src_raw)[e];
        d = ((const int*)dst_raw)[e];
    }
}

// ---------------- kernel 1: zero counts + dtype sniff ----------------
__global__ void zero_sniff_kernel(const void* __restrict__ src) {
    int i = blockIdx.x * blockDim.x + threadIdx.x;
    if (i < N_NODES) g_cnt[i] = 0;
    if (i == 0) {
        const long long* p = (const long long*)src;
        int ok = 1;
        #pragma unroll 1
        for (int q = 0; q < 64; q++) {
            long long v = p[q];
            if (v < 0 || v >= N_NODES) { ok = 0; break; }
        }
        g_is64 = ok;
    }
}

// ---------------- CSR build (validated) ----------------
__global__ void count_kernel(const void* __restrict__ src_raw,
                             const void* __restrict__ dst_raw) {
    const int is64 = g_is64;
    int idx = blockIdx.x * blockDim.x + threadIdx.x;
    int stride = gridDim.x * blockDim.x;
    for (int e = idx; e < N_EDGES; e += stride) {
        int s, d;
        load_edge(src_raw, dst_raw, e, is64, s, d);
        if ((unsigned)s < N_NODES && (unsigned)d < N_NODES)
            atomicAdd(&g_cnt[d], 1);
    }
}

__global__ void scan1_kernel() {
    __shared__ int sm[256];
    int gi = blockIdx.x * 256 + threadIdx.x;
    sm[threadIdx.x] = (gi < N_NODES) ? g_cnt[gi] : 0;
    __syncthreads();
    for (int off = 128; off > 0; off >>= 1) {
        if (threadIdx.x < off) sm[threadIdx.x] += sm[threadIdx.x + off];
        __syncthreads();
    }
    if (threadIdx.x == 0) g_bsum[blockIdx.x] = sm[0];
}
__global__ void scan2_kernel() {
    __shared__ int sm[512];
    int t = threadIdx.x;
    sm[t] = (t < NB_SCAN) ? g_bsum[t] : 0;
    __syncthreads();
    for (int off = 1; off < 512; off <<= 1) {
        int v = (t >= off) ? sm[t - off] : 0;
        __syncthreads();
        sm[t] += v;
        __syncthreads();
    }
    int ex = (t == 0) ? 0 : sm[t - 1];
    if (t < NB_SCAN) g_bsum[t] = ex;
    if (t == NB_SCAN) g_rs[N_NODES] = sm[NB_SCAN - 1];
}
__global__ void scan3_kernel() {
    __shared__ int sm[256];
    int b = blockIdx.x, t = threadIdx.x;
    int gi = b * 256 + t;
    int c = (gi < N_NODES) ? g_cnt[gi] : 0;
    sm[t] = c;
    __syncthreads();
    for (int off = 1; off < 256; off <<= 1) {
        int v = (t >= off) ? sm[t - off] : 0;
        __syncthreads();
        sm[t] += v;
        __syncthreads();
    }
    int ex = sm[t] - c;
    if (gi < N_NODES) {
        g_rs[gi] = g_bsum[b] + ex;
        g_cnt[gi] = 0;
    }
}

__global__ void fill_kernel(const void* __restrict__ src_raw,
                            const void* __restrict__ dst_raw) {
    const int is64 = g_is64;
    int idx = blockIdx.x * blockDim.x + threadIdx.x;
    int stride = gridDim.x * blockDim.x;
    for (int e = idx; e < N_EDGES; e += stride) {
        int s, d;
        load_edge(src_raw, dst_raw, e, is64, s, d);
        if ((unsigned)s < N_NODES && (unsigned)d < N_NODES) {
            int pos = atomicAdd(&g_cnt[d], 1);
            g_esrc[g_rs[d] + pos] = s;
        }
    }
}

// ---------------- fused kernel: gather + mma.sync tf32 GEMM ----------------
// SMEM: sB[32768 fp32] = W' fragment-linear (built once), then
//       sX[2][8192 fp32] = X tiles, A-fragment-linear + XOR swizzle.
// 384 threads: warps 0-3 compute (mma.sync, warp w owns cols w*32..w*32+31),
//              warps 4-11 gather (4 rows each). Ping-pong, 1 sync/tile.
//
// A frag (m16n8k8 row): a_reg = {(c<4,rr<8),(c<4,rr>=8),(c>=4,rr<8),(c>=4,rr>=8)}
//   thread t = (rr&7)*4 + (c&3). Stored at word:
//   (ks*2+rb)*128 + ((t*4) ^ ((ks&7)*4)) + reg   -> compute reads 1 LDS.128/frag.
// B frag (col): b_reg = (k&7)>=4, thread t = (n&7)*4 + (k&3). Stored at word:
//   (ks*16+nb)*64 + t*2 + reg                    -> compute reads 1 LDS.64/frag.
__global__ __launch_bounds__(384, 1)
void fused_kernel(const float* __restrict__ h,
                  const float* __restrict__ Ws,
                  const float* __restrict__ Wn,
                  float* __restrict__ out) {
    extern __shared__ float sm[];
    float* sB = sm;            // 32768 floats (128 KB)
    float* sX = sm + 32768;    // 2 x 8192 floats (64 KB)

    int tid = threadIdx.x, wid = tid >> 5, lane = tid & 31;
    const bool is_gather = (wid >= 4);

    // ---- gather: fill X tile (A-fragment layout, swizzled) ----
    auto fill_tile = [&](int tile, int buf) {
        float* bX = sX + buf * 8192;
        int gwid = wid - 4;                       // 0..7
        const int sw4 = ((lane >> 1) & 7) * 4;    // XOR swizzle for this lane's ks
        const int regsel = (lane & 1) ? 2 : 0;    // c>=4 half
        const int base_s = ((lane >> 1) * 2) * 128;        // self ks = lane>>1
        const int base_n = (((lane >> 1) + 16) * 2) * 128; // neigh ks = 16+lane>>1
        #pragma unroll 1
        for (int rr4 = 0; rr4 < 4; rr4++) {
            int r = gwid * 4 + rr4;
            int row = tile * TILE + r;
            int rb = r >> 4, rr = r & 15;
            int reg = regsel + ((rr >= 8) ? 1 : 0);
            int tb = (rr & 7) * 16;
            int bs = base_s + rb * 128;
            int bn = base_n + rb * 128;

            float4 self = reinterpret_cast<const float4*>(h + (size_t)row * D)[lane];
            int beg = g_rs[row], end = g_rs[row + 1];
            float inv = 1.0f / fmaxf((float)(end - beg), 1.0f);
            float4 acc = make_float4(0.f, 0.f, 0.f, 0.f);
            int e = beg;
            #pragma unroll 1
            for (; e + 8 <= end; e += 8) {
                int si[8];
                #pragma unroll
                for (int q = 0; q < 8; q++) si[q] = g_esrc[e + q];
                float4 v[8];
                #pragma unroll
                for (int q = 0; q < 8; q++)
                    v[q] = reinterpret_cast<const float4*>(h + (size_t)si[q] * D)[lane];
                #pragma unroll
                for (int q = 0; q < 8; q++) {
                    acc.x += v[q].x; acc.y += v[q].y;
                    acc.z += v[q].z; acc.w += v[q].w;
                }
            }
            #pragma unroll 1
            for (; e < end; e++) {
                int s0 = g_esrc[e];
                float4 v0 = reinterpret_cast<const float4*>(h + (size_t)s0 * D)[lane];
                acc.x += v0.x; acc.y += v0.y; acc.z += v0.z; acc.w += v0.w;
            }
            acc.x *= inv; acc.y *= inv; acc.z *= inv; acc.w *= inv;

            bX[bs + ((tb + 0) ^ sw4) + reg] = self.x;
            bX[bs + ((tb + 4) ^ sw4) + reg] = self.y;
            bX[bs + ((tb + 8) ^ sw4) + reg] = self.z;
            bX[bs + ((tb + 12) ^ sw4) + reg] = self.w;
            bX[bn + ((tb + 0) ^ sw4) + reg] = acc.x;
            bX[bn + ((tb + 4) ^ sw4) + reg] = acc.y;
            bX[bn + ((tb + 8) ^ sw4) + reg] = acc.z;
            bX[bn + ((tb + 12) ^ sw4) + reg] = acc.w;
        }
    };

    // ---- prologue: compute warps build B frags; gather warps fill buf0 ----
    int t0 = blockIdx.x;
    if (is_gather) {
        if (t0 < NTILES) fill_tile(t0, 0);
    } else {
        for (int idx = tid; idx < 32768; idx += 128) {
            int k = idx >> 7, n = idx & 127;
            float w = (k < 128) ? Ws[k * 128 + n] : Wn[(k - 128) * 128 + n];
            int ks = k >> 3, nb = n >> 3;
            int ft = (n & 7) * 4 + (k & 3);
            int reg = ((k & 7) >= 4) ? 1 : 0;
            sB[(ks * 16 + nb) * 64 + ft * 2 + reg] = w;
        }
    }
    __syncthreads();

    int p = 0;
    const int nbg0 = wid * 4;   // compute: global n-block base (cols wid*32..+31)

    for (int t = t0; t < NTILES; t += gridDim.x) {
        if (is_gather) {
            int tn = t + gridDim.x;
            if (tn < NTILES) fill_tile(tn, p ^ 1);
        } else {
            float* bX = sX + p * 8192;
            float d[2][4][4];
            #pragma unroll
            for (int rb = 0; rb < 2; rb++)
                #pragma unroll
                for (int nb = 0; nb < 4; nb++)
                    #pragma unroll
                    for (int q = 0; q < 4; q++) d[rb][nb][q] = 0.f;

            #pragma unroll 1
            for (int ks = 0; ks < 32; ks++) {
                uint32_t ah[2][4], al[2][4];
                #pragma unroll
                for (int rb = 0; rb < 2; rb++) {
                    const float4 ar = *reinterpret_cast<const float4*>(
                        bX + (ks * 2 + rb) * 128 + ((lane * 4) ^ ((ks & 7) * 4)));
                    ah[rb][0] = f2tf(ar.x);
                    ah[rb][1] = f2tf(ar.y);
                    ah[rb][2] = f2tf(ar.z);
                    ah[rb][3] = f2tf(ar.w);
                    al[rb][0] = f2tf(ar.x - __uint_as_float(ah[rb][0]));
                    al[rb][1] = f2tf(ar.y - __uint_as_float(ah[rb][1]));
                    al[rb][2] = f2tf(ar.z - __uint_as_float(ah[rb][2]));
                    al[rb][3] = f2tf(ar.w - __uint_as_float(ah[rb][3]));
                }
                #pragma unroll
                for (int nb = 0; nb < 4; nb++) {
                    const float2 br = *reinterpret_cast<const float2*>(
                        sB + (ks * 16 + nbg0 + nb) * 64 + lane * 2);
                    uint32_t bh[2], bl[2];
                    bh[0] = f2tf(br.x);
                    bh[1] = f2tf(br.y);
                    bl[0] = f2tf(br.x - __uint_as_float(bh[0]));
                    bl[1] = f2tf(br.y - __uint_as_float(bh[1]));
                    #pragma unroll
                    for (int rb = 0; rb < 2; rb++) {
                        mma_tf32(d[rb][nb], ah[rb], bh);
                        mma_tf32(d[rb][nb], al[rb], bh);
                        mma_tf32(d[rb][nb], ah[rb], bl);
                    }
                }
            }

            // epilogue: D frag -> gmem (thread t: row rb*16 + t/4 (+8), col (t%4)*2)
            int rbase = t * TILE;
            #pragma unroll
            for (int rb = 0; rb < 2; rb++) {
                int r0 = rbase + rb * 16 + (lane >> 2);
                #pragma unroll
                for (int nb = 0; nb < 4; nb++) {
                    int c0 = (nbg0 + nb) * 8 + (lane & 3) * 2;
                    *reinterpret_cast<float2*>(out + (size_t)r0 * D + c0) =
                        make_float2(d[rb][nb][0], d[rb][nb][1]);
                    *reinterpret_cast<float2*>(out + (size_t)(r0 + 8) * D + c0) =
                        make_float2(d[rb][nb][2], d[rb][nb][3]);
                }
            }
        }
        __syncthreads();
        p ^= 1;
    }
}

// ---------------- launch ----------------
extern "C" void kernel_launch(void* const* d_in, const int* in_sizes, int n_in,
                              void* d_out, int out_size) {
    const float* h      = (const float*)d_in[0];
    const void*  src    = d_in[1];
    const void*  dst    = d_in[2];
    const float* Wself  = (const float*)d_in[3];
    const float* Wneigh = (const float*)d_in[4];
    float*       out    = (float*)d_out;

    static bool attr_set = false;
    if (!attr_set) {
        cudaFuncSetAttribute(fused_kernel,
                             cudaFuncAttributeMaxDynamicSharedMemorySize,
                             196608);
        attr_set = true;
    }

    zero_sniff_kernel<<<NB_SCAN, 256>>>(src);
    count_kernel<<<2048, 256>>>(src, dst);
    scan1_kernel<<<NB_SCAN, 256>>>();
    scan2_kernel<<<1, 512>>>();
    scan3_kernel<<<NB_SCAN, 256>>>();
    fill_kernel<<<2048, 256>>>(src, dst);
    fused_kernel<<<152, 384, 196608>>>(h, Wself, Wneigh, out);
}